// round 1
// baseline (speedup 1.0000x reference)
#include <cuda_runtime.h>
#include <cuda_bf16.h>
#include <math.h>

#define BB    8
#define CIN   256
#define CMID  128
#define PP    3600            // 60*60 positions per batch image
#define NPOS  (BB * PP)       // 28800

// -------- device scratch (alloc at module load; no runtime alloc) --------
__device__ float g_hidden[(size_t)2 * BB * PP * CMID];   // conv output, [s][b*P+p][c]
__device__ float g_feat  [(size_t)2 * BB * PP * CMID];   // normalized features
__device__ float g_sum[256], g_sumsq[256];               // per-pass BN reductions
__device__ float g_scale[256], g_shift[256];             // folded BN affine
__device__ float g_loss;

// ---------------------------------------------------------------------
__global__ void zero_kernel() {
    int t = threadIdx.x;
    if (t < 256) { g_sum[t] = 0.f; g_sumsq[t] = 0.f; }
    if (t == 0) g_loss = 0.f;
}

// ---------------------------------------------------------------------
// Kernel A: y[b,p,co] = conv_w[co,:] . relu(x[b,:,p]) + conv_b[co]
// also accumulates per-channel sum / sumsq for BatchNorm batch stats.
// grid (57, 8, 2), block 256.  Tile: 64 positions x 128 cout, K-chunk 32.
__global__ void __launch_bounds__(256) conv_kernel(
    const float* __restrict__ x0, const float* __restrict__ x1,
    const float* __restrict__ cw, const float* __restrict__ cb)
{
    const int s = blockIdx.z, b = blockIdx.y;
    const int pbase = blockIdx.x * 64;
    const float* x = (s == 0 ? x0 : x1) + (size_t)b * CIN * PP;

    __shared__ float xs[32][68];
    __shared__ float ws[128][33];
    __shared__ float ssum[128], ssq[128];

    const int t = threadIdx.x;
    if (t < 128) { ssum[t] = 0.f; ssq[t] = 0.f; }
    const int tx = t & 15, ty = t >> 4;
    const int p0 = tx * 4, co0 = ty * 8;

    float acc[4][8];
#pragma unroll
    for (int r = 0; r < 4; r++)
#pragma unroll
        for (int u = 0; u < 8; u++) acc[r][u] = 0.f;

    for (int kc = 0; kc < CIN; kc += 32) {
        __syncthreads();
#pragma unroll
        for (int u = 0; u < 2; u++) {           // xs: 32ci x 64p = 512 float4
            int idx = u * 256 + t;
            int ci = idx >> 4, f = (idx & 15) * 4;
            float4 v = make_float4(0.f, 0.f, 0.f, 0.f);
            if (pbase + f < PP)
                v = *(const float4*)(x + (size_t)(kc + ci) * PP + pbase + f);
            xs[ci][f + 0] = fmaxf(v.x, 0.f);
            xs[ci][f + 1] = fmaxf(v.y, 0.f);
            xs[ci][f + 2] = fmaxf(v.z, 0.f);
            xs[ci][f + 3] = fmaxf(v.w, 0.f);
        }
#pragma unroll
        for (int u = 0; u < 4; u++) {           // ws: 128co x 32ci = 1024 float4
            int idx = u * 256 + t;
            int co = idx >> 3, f = (idx & 7) * 4;
            float4 v = *(const float4*)(cw + (size_t)co * CIN + kc + f);
            ws[co][f + 0] = v.x; ws[co][f + 1] = v.y;
            ws[co][f + 2] = v.z; ws[co][f + 3] = v.w;
        }
        __syncthreads();
#pragma unroll
        for (int ci = 0; ci < 32; ci++) {
            float4 xv = *(const float4*)&xs[ci][p0];
#pragma unroll
            for (int u = 0; u < 8; u++) {
                float w = ws[co0 + u][ci];
                acc[0][u] = fmaf(xv.x, w, acc[0][u]);
                acc[1][u] = fmaf(xv.y, w, acc[1][u]);
                acc[2][u] = fmaf(xv.z, w, acc[2][u]);
                acc[3][u] = fmaf(xv.w, w, acc[3][u]);
            }
        }
    }

    float bias[8], lsum[8], lsq[8];
#pragma unroll
    for (int u = 0; u < 8; u++) { bias[u] = cb[co0 + u]; lsum[u] = 0.f; lsq[u] = 0.f; }

    float* hid = g_hidden + (size_t)s * (BB * (size_t)PP * CMID) + (size_t)b * PP * CMID;
#pragma unroll
    for (int r = 0; r < 4; r++) {
        int p = pbase + p0 + r;
        float y[8];
#pragma unroll
        for (int u = 0; u < 8; u++) y[u] = acc[r][u] + bias[u];
        if (p < PP) {
            float4 v0 = make_float4(y[0], y[1], y[2], y[3]);
            float4 v1 = make_float4(y[4], y[5], y[6], y[7]);
            *(float4*)(hid + (size_t)p * CMID + co0)     = v0;
            *(float4*)(hid + (size_t)p * CMID + co0 + 4) = v1;
#pragma unroll
            for (int u = 0; u < 8; u++) { lsum[u] += y[u]; lsq[u] += y[u] * y[u]; }
        }
    }
#pragma unroll
    for (int u = 0; u < 8; u++) {
        atomicAdd(&ssum[co0 + u], lsum[u]);
        atomicAdd(&ssq [co0 + u], lsq [u]);
    }
    __syncthreads();
    if (t < 128) {
        atomicAdd(&g_sum  [s * 128 + t], ssum[t]);
        atomicAdd(&g_sumsq[s * 128 + t], ssq [t]);
    }
}

// ---------------------------------------------------------------------
__global__ void stats_kernel(const float* __restrict__ gamma,
                             const float* __restrict__ beta)
{
    int s = blockIdx.x, c = threadIdx.x;
    if (c < 128) {
        float n = (float)NPOS;
        float mean = g_sum[s * 128 + c] / n;
        float var  = g_sumsq[s * 128 + c] / n - mean * mean;
        float rs   = rsqrtf(var + 1e-5f);
        float scl  = gamma[c] * rs;
        g_scale[s * 128 + c] = scl;
        g_shift[s * 128 + c] = beta[c] - mean * scl;
    }
}

// ---------------------------------------------------------------------
// Kernel C: feat[b,p,o] = normalize_o( lin_w[o,:] . relu(scale*h + shift) + lin_b[o] )
// grid (57, 8, 2), block 256. Tile 64 pos x 128 out, K=128 chunked by 32.
__global__ void __launch_bounds__(256) feat_kernel(
    const float* __restrict__ lw, const float* __restrict__ lb)
{
    const int s = blockIdx.z, b = blockIdx.y;
    const int pbase = blockIdx.x * 64;

    __shared__ float hs[32][68];
    __shared__ float ws[128][33];
    __shared__ float psum[64];

    const int t = threadIdx.x;
    if (t < 64) psum[t] = 0.f;
    const int tx = t & 15, ty = t >> 4;
    const int p0 = tx * 4, co0 = ty * 8;

    const float* hid = g_hidden + (size_t)s * (BB * (size_t)PP * CMID) + (size_t)b * PP * CMID;
    const float* sc = g_scale + s * 128;
    const float* sh = g_shift + s * 128;

    float acc[4][8];
#pragma unroll
    for (int r = 0; r < 4; r++)
#pragma unroll
        for (int u = 0; u < 8; u++) acc[r][u] = 0.f;

    for (int kc = 0; kc < CMID; kc += 32) {
        __syncthreads();
#pragma unroll
        for (int u = 0; u < 2; u++) {           // hs (transposed, affine+relu on load)
            int idx = u * 256 + t;
            int p = idx >> 3, f = (idx & 7) * 4;
            float4 v = make_float4(0.f, 0.f, 0.f, 0.f);
            int gp = pbase + p;
            if (gp < PP) v = *(const float4*)(hid + (size_t)gp * CMID + kc + f);
            hs[f + 0][p] = fmaxf(fmaf(v.x, sc[kc + f + 0], sh[kc + f + 0]), 0.f);
            hs[f + 1][p] = fmaxf(fmaf(v.y, sc[kc + f + 1], sh[kc + f + 1]), 0.f);
            hs[f + 2][p] = fmaxf(fmaf(v.z, sc[kc + f + 2], sh[kc + f + 2]), 0.f);
            hs[f + 3][p] = fmaxf(fmaf(v.w, sc[kc + f + 3], sh[kc + f + 3]), 0.f);
        }
#pragma unroll
        for (int u = 0; u < 4; u++) {
            int idx = u * 256 + t;
            int co = idx >> 3, f = (idx & 7) * 4;
            float4 v = *(const float4*)(lw + (size_t)co * CMID + kc + f);
            ws[co][f + 0] = v.x; ws[co][f + 1] = v.y;
            ws[co][f + 2] = v.z; ws[co][f + 3] = v.w;
        }
        __syncthreads();
#pragma unroll
        for (int ci = 0; ci < 32; ci++) {
            float4 xv = *(const float4*)&hs[ci][p0];
#pragma unroll
            for (int u = 0; u < 8; u++) {
                float w = ws[co0 + u][ci];
                acc[0][u] = fmaf(xv.x, w, acc[0][u]);
                acc[1][u] = fmaf(xv.y, w, acc[1][u]);
                acc[2][u] = fmaf(xv.z, w, acc[2][u]);
                acc[3][u] = fmaf(xv.w, w, acc[3][u]);
            }
        }
    }

    float bias[8];
#pragma unroll
    for (int u = 0; u < 8; u++) bias[u] = lb[co0 + u];
    float y[4][8];
#pragma unroll
    for (int r = 0; r < 4; r++) {
        float sq = 0.f;
#pragma unroll
        for (int u = 0; u < 8; u++) {
            y[r][u] = acc[r][u] + bias[u];
            sq = fmaf(y[r][u], y[r][u], sq);
        }
        atomicAdd(&psum[p0 + r], sq);
    }
    __syncthreads();

    float* ft = g_feat + (size_t)s * (BB * (size_t)PP * CMID) + (size_t)b * PP * CMID;
#pragma unroll
    for (int r = 0; r < 4; r++) {
        int p = pbase + p0 + r;
        if (p < PP) {
            float inv = 1.f / fmaxf(sqrtf(psum[p0 + r]), 1e-12f);
            float4 v0 = make_float4(y[r][0] * inv, y[r][1] * inv, y[r][2] * inv, y[r][3] * inv);
            float4 v1 = make_float4(y[r][4] * inv, y[r][5] * inv, y[r][6] * inv, y[r][7] * inv);
            *(float4*)(ft + (size_t)p * CMID + co0)     = v0;
            *(float4*)(ft + (size_t)p * CMID + co0 + 4) = v1;
        }
    }
}

// ---------------------------------------------------------------------
// Kernel D: fused logits GEMM + logsumexp + pos-dot + loss reduction.
// For each (b, 64-row tile of o): stream 64-row tiles of t, accumulate
// sum_j exp(o_i.t_j / T) per row (no max needed: |logit| <= 14.3).
// grid (57, 8), block 256, dynamic smem = 2*64*132 + 64 floats.
__global__ void __launch_bounds__(256) loss_kernel()
{
    extern __shared__ float sm[];
    float* os     = sm;                 // 64 x 132
    float* ts     = sm + 64 * 132;      // 64 x 132
    float* rowsum = sm + 2 * 64 * 132;  // 64
    __shared__ float cred[256];

    const int b  = blockIdx.y;
    const int i0 = blockIdx.x * 64;
    const int t  = threadIdx.x, tx = t & 15, ty = t >> 4;
    const float invT = 1.0f / 0.07f;

    const float* fo  = g_feat + (size_t)b * PP * CMID;
    const float* ftg = g_feat + (size_t)BB * PP * CMID + (size_t)b * PP * CMID;

    if (t < 64) rowsum[t] = 0.f;

#pragma unroll
    for (int u = 0; u < 8; u++) {           // load o tile
        int idx = u * 256 + t;
        int row = idx >> 5, f = (idx & 31) * 4;
        float4 v = make_float4(0.f, 0.f, 0.f, 0.f);
        if (i0 + row < PP) v = *(const float4*)(fo + (size_t)(i0 + row) * CMID + f);
        os[row * 132 + f + 0] = v.x; os[row * 132 + f + 1] = v.y;
        os[row * 132 + f + 2] = v.z; os[row * 132 + f + 3] = v.w;
    }

    float sacc[4] = {0.f, 0.f, 0.f, 0.f};

    for (int jt = 0; jt < 57; jt++) {
        int j0 = jt * 64;
        __syncthreads();
#pragma unroll
        for (int u = 0; u < 8; u++) {       // load t tile
            int idx = u * 256 + t;
            int row = idx >> 5, f = (idx & 31) * 4;
            float4 v = make_float4(0.f, 0.f, 0.f, 0.f);
            if (j0 + row < PP) v = *(const float4*)(ftg + (size_t)(j0 + row) * CMID + f);
            ts[row * 132 + f + 0] = v.x; ts[row * 132 + f + 1] = v.y;
            ts[row * 132 + f + 2] = v.z; ts[row * 132 + f + 3] = v.w;
        }
        __syncthreads();

        float acc[4][4];
#pragma unroll
        for (int r = 0; r < 4; r++)
#pragma unroll
            for (int q = 0; q < 4; q++) acc[r][q] = 0.f;

#pragma unroll
        for (int c4 = 0; c4 < 32; c4++) {
            float4 ov[4], tv[4];
#pragma unroll
            for (int r = 0; r < 4; r++) ov[r] = *(const float4*)&os[(ty * 4 + r) * 132 + c4 * 4];
#pragma unroll
            for (int q = 0; q < 4; q++) tv[q] = *(const float4*)&ts[(tx * 4 + q) * 132 + c4 * 4];
#pragma unroll
            for (int r = 0; r < 4; r++)
#pragma unroll
                for (int q = 0; q < 4; q++) {
                    acc[r][q] = fmaf(ov[r].x, tv[q].x, acc[r][q]);
                    acc[r][q] = fmaf(ov[r].y, tv[q].y, acc[r][q]);
                    acc[r][q] = fmaf(ov[r].z, tv[q].z, acc[r][q]);
                    acc[r][q] = fmaf(ov[r].w, tv[q].w, acc[r][q]);
                }
        }
#pragma unroll
        for (int r = 0; r < 4; r++)
#pragma unroll
            for (int q = 0; q < 4; q++) {
                int j = j0 + tx * 4 + q;
                if (j < PP) sacc[r] += __expf(acc[r][q] * invT);
            }
    }
    __syncthreads();
#pragma unroll
    for (int r = 0; r < 4; r++) atomicAdd(&rowsum[ty * 4 + r], sacc[r]);
    __syncthreads();

    // pos dot + per-row contribution (4 threads per row)
    float contrib = 0.f;
    {
        int row = t >> 2, sub = t & 3;
        int ig = i0 + row;
        if (ig < PP) {
            const float* trow = ftg + (size_t)ig * CMID + sub * 32;
            const float* orow = &os[row * 132 + sub * 32];
            float pd = 0.f;
#pragma unroll
            for (int k = 0; k < 32; k++) pd = fmaf(orow[k], trow[k], pd);
            pd += __shfl_down_sync(0xffffffffu, pd, 1);
            pd += __shfl_down_sync(0xffffffffu, pd, 2);
            if (sub == 0) contrib = logf(rowsum[row]) - pd * invT;
        }
    }
    cred[t] = contrib;
    __syncthreads();
#pragma unroll
    for (int off = 128; off > 0; off >>= 1) {
        if (t < off) cred[t] += cred[t + off];
        __syncthreads();
    }
    if (t == 0) atomicAdd(&g_loss, cred[0]);
}

// ---------------------------------------------------------------------
__global__ void finalize_kernel(float* __restrict__ out) {
    out[0] = g_loss * (1.0f / (float)NPOS);
}

// ---------------------------------------------------------------------
extern "C" void kernel_launch(void* const* d_in, const int* in_sizes, int n_in,
                              void* d_out, int out_size)
{
    const float* x0    = (const float*)d_in[0];
    const float* x1    = (const float*)d_in[1];
    const float* cw    = (const float*)d_in[2];
    const float* cb    = (const float*)d_in[3];
    const float* gamma = (const float*)d_in[4];
    const float* beta  = (const float*)d_in[5];
    const float* lw    = (const float*)d_in[6];
    const float* lb    = (const float*)d_in[7];
    float* out = (float*)d_out;

    size_t lsm = (size_t)(2 * 64 * 132 + 64) * sizeof(float);  // 67840 B
    cudaFuncSetAttribute((const void*)loss_kernel,
                         cudaFuncAttributeMaxDynamicSharedMemorySize, (int)lsm);

    zero_kernel<<<1, 256>>>();
    conv_kernel<<<dim3(57, 8, 2), 256>>>(x0, x1, cw, cb);
    stats_kernel<<<2, 128>>>(gamma, beta);
    feat_kernel<<<dim3(57, 8, 2), 256>>>(lw, lb);
    loss_kernel<<<dim3(57, 8), 256, lsm>>>();
    finalize_kernel<<<1, 1>>>(out);
}